// round 13
// baseline (speedup 1.0000x reference)
#include <cuda_runtime.h>
#include <cuda_fp16.h>
#include <cstdint>
#include <cstddef>

// ---------------- problem constants ----------------
#define T_TOK 4096
#define D_DIM 1024
#define F_DIM 2816
#define F2_DIM 5632
#define N_EXP 8
#define TK 8192

// ---------------- tiling ----------------
// fp16, warp-autonomous: BM=128, BN=64, BK=32, 256 threads,
// warps 2m x 2n x 2k; each warp owns private smem buffers for its
// 64m x 32n x k16 operands. 4 private stages, 3 in flight, NO CTA
// barrier in the mainloop. 2 CTAs/SM.
#define N_ST 4
#define W_ST 3072                         // per-warp stage: A 2KB + B 1KB
#define W_REGION (N_ST * W_ST)            // 12 KB per warp
#define SMEM_BYTES (8 * W_REGION)         // 96 KB per CTA
#define GRIDX 9

// ---------------- device scratch ----------------
__device__ int    g_offsets[N_EXP + 1];
__device__ int    g_tok[TK];
__device__ int    g_pos[TK];
__device__ float  g_wt[TK];
__device__ __half g_xh[(size_t)T_TOK * D_DIM];
__device__ __half g_wguh[(size_t)N_EXP * F2_DIM * D_DIM];
__device__ __half g_wdh[(size_t)N_EXP * D_DIM * F_DIM];
__device__ __half g_h[(size_t)TK * F_DIM];
__device__ float  g_o[(size_t)TK * D_DIM];

// ---------------- helpers ----------------
__device__ __forceinline__ uint32_t cvta_s(const void* p) {
    return (uint32_t)__cvta_generic_to_shared(p);
}
__device__ __forceinline__ void cpasync16(uint32_t smem_addr, const void* gptr) {
    asm volatile("cp.async.cg.shared.global [%0], [%1], 16;" ::"r"(smem_addr), "l"(gptr));
}
__device__ __forceinline__ void cp_commit() { asm volatile("cp.async.commit_group;"); }
__device__ __forceinline__ void cp_waitg(int left) {
    if (left <= 0) asm volatile("cp.async.wait_group 0;");
    else if (left == 1) asm volatile("cp.async.wait_group 1;");
    else asm volatile("cp.async.wait_group 2;");
}
__device__ __forceinline__ void ldsm4(uint32_t r[4], uint32_t addr) {
    asm volatile("ldmatrix.sync.aligned.m8n8.x4.shared.b16 {%0,%1,%2,%3}, [%4];"
                 : "=r"(r[0]), "=r"(r[1]), "=r"(r[2]), "=r"(r[3]) : "r"(addr));
}
__device__ __forceinline__ void mma_f16(float c[4], const uint32_t a[4],
                                        uint32_t b0, uint32_t b1) {
    asm volatile(
        "mma.sync.aligned.m16n8k16.row.col.f32.f16.f16.f32 "
        "{%0,%1,%2,%3},{%4,%5,%6,%7},{%8,%9},{%0,%1,%2,%3};"
        : "+f"(c[0]), "+f"(c[1]), "+f"(c[2]), "+f"(c[3])
        : "r"(a[0]), "r"(a[1]), "r"(a[2]), "r"(a[3]), "r"(b0), "r"(b1));
}

// ---------------- convert f32 inputs to fp16 ----------------
__global__ void cvt_all(const float4* __restrict__ x, const float4* __restrict__ wgu,
                        const float4* __restrict__ wd) {
    const int NX = T_TOK * D_DIM / 4;
    const int NG = N_EXP * F2_DIM * D_DIM / 4;
    const int ND = N_EXP * D_DIM * F_DIM / 4;
    const int total = NX + NG + ND;
    for (int i = blockIdx.x * blockDim.x + threadIdx.x; i < total;
         i += gridDim.x * blockDim.x) {
        const float4* s;
        __half2* d;
        int j;
        if (i < NX)           { s = x;   d = (__half2*)g_xh;   j = i; }
        else if (i < NX + NG) { s = wgu; d = (__half2*)g_wguh; j = i - NX; }
        else                  { s = wd;  d = (__half2*)g_wdh;  j = i - NX - NG; }
        float4 v = s[j];
        d[2 * j]     = __float22half2_rn(make_float2(v.x, v.y));
        d[2 * j + 1] = __float22half2_rn(make_float2(v.z, v.w));
    }
}

// ---------------- routing ----------------
__global__ void routing_kernel(const void* sel_raw, const float* __restrict__ rw) {
    __shared__ int sc[N_EXP];
    __shared__ int scur[N_EXP];
    __shared__ int smode;
    int tid = threadIdx.x;
    if (tid < N_EXP) sc[tid] = 0;
    if (tid == 0) {
        const int* s32 = (const int*)sel_raw;
        int any = 0;
        #pragma unroll
        for (int i = 0; i < 8; i++) any |= s32[2 * i + 1];
        smode = any ? 0 : 1;  // 1 = int64
    }
    __syncthreads();
    int mode = smode;
    const long long* s64 = (const long long*)sel_raw;
    const int* s32 = (const int*)sel_raw;
    for (int i = tid; i < TK; i += blockDim.x) {
        int e = mode ? (int)s64[i] : s32[i];
        atomicAdd(&sc[e], 1);
    }
    __syncthreads();
    if (tid == 0) {
        int off = 0;
        for (int e = 0; e < N_EXP; e++) { g_offsets[e] = off; scur[e] = off; off += sc[e]; }
        g_offsets[N_EXP] = off;
    }
    __syncthreads();
    for (int i = tid; i < TK; i += blockDim.x) {
        int e = mode ? (int)s64[i] : s32[i];
        int p = atomicAdd(&scur[e], 1);
        g_tok[p] = i >> 1;
        g_pos[p] = i;
        g_wt[p] = rw[i];
    }
}

// ---------------- warp-autonomous fp16 mainloop ----------------
// Warp-private stage (3KB): A[ c*1024 + r*16 ] 64 rows x 2 chunks,
//                           B at +2048 [ c*512 + r*16 ] 32 rows x 2 chunks.
// Per stage, lane loads: A rows (lane, lane+32) x 2 chunks, B row lane x 2.
// koff (halves) = wk*16 selects this warp's k16 within BK=32.
// No CTA barrier inside: wait_group + __syncwarp only.
__device__ __forceinline__ void mma_loop(uint32_t wb, const __half* a_ptr0,
                                         const __half* a_ptr1, const __half* b_ptr,
                                         int koff, int KT, float cc[4][4][4]) {
    const int lane = threadIdx.x & 31;

    // ldsm addresses (stage-relative)
    const uint32_t csel = (uint32_t)(lane >> 4);
    const uint32_t rsel = (uint32_t)(lane & 15);
    uint32_t a_ls[4], b_ls[2];
    #pragma unroll
    for (int mt = 0; mt < 4; mt++)
        a_ls[mt] = csel * 1024 + (mt * 16 + rsel) * 16;
    #pragma unroll
    for (int n2 = 0; n2 < 2; n2++)
        b_ls[n2] = 2048 + csel * 512 + (n2 * 16 + rsel) * 16;

    // cp.async dst offsets (stage-relative)
    const uint32_t dA0 = (uint32_t)(lane * 16);
    const uint32_t dA1 = dA0 + 512;
    const uint32_t dA2 = dA0 + 1024;
    const uint32_t dA3 = dA0 + 1536;
    const uint32_t dB0 = 2048 + dA0;
    const uint32_t dB1 = dB0 + 512;

    auto load_stage = [&](int kt) {
        const uint32_t sb = wb + (uint32_t)((kt & (N_ST - 1)) * W_ST);
        const int o0 = kt * 32 + koff;       // halves
        cpasync16(sb + dA0, a_ptr0 + o0);
        cpasync16(sb + dA1, a_ptr1 + o0);
        cpasync16(sb + dA2, a_ptr0 + o0 + 8);
        cpasync16(sb + dA3, a_ptr1 + o0 + 8);
        cpasync16(sb + dB0, b_ptr + o0);
        cpasync16(sb + dB1, b_ptr + o0 + 8);
        cp_commit();
    };

    #pragma unroll
    for (int s = 0; s < 3; s++) load_stage(s);

    for (int kt = 0; kt < KT; kt++) {
        const int rem = KT - 1 - kt;
        cp_waitg(rem < 2 ? rem : 2);
        __syncwarp();
        if (kt + 3 < KT) load_stage(kt + 3);

        const uint32_t sb = wb + (uint32_t)((kt & (N_ST - 1)) * W_ST);
        uint32_t a[4][4], b[2][4];
        #pragma unroll
        for (int mt = 0; mt < 4; mt++)
            ldsm4(a[mt], sb + a_ls[mt]);
        #pragma unroll
        for (int n2 = 0; n2 < 2; n2++)
            ldsm4(b[n2], sb + b_ls[n2]);
        // b regs: r0=b0(oct0), r1=b0(oct1), r2=b1(oct0), r3=b1(oct1)
        #pragma unroll
        for (int mt = 0; mt < 4; mt++)
            #pragma unroll
            for (int nt = 0; nt < 4; nt++)
                mma_f16(cc[mt][nt], a[mt], b[nt >> 1][nt & 1],
                        b[nt >> 1][2 + (nt & 1)]);
    }
}

// k-split reduction: warp pairs (w, w+4) share (wm, wn); 8KB slot each.
// Overlaps pipeline smem -> bracketed by CTA barriers.
__device__ __forceinline__ void ksplit_reduce(uint32_t smem0, int warp, int lane,
                                              int wk, float cc[4][4][4]) {
    __syncthreads();
    const uint32_t redb = smem0 + (uint32_t)((warp & 3) * 8192);
    if (wk == 1) {
        #pragma unroll
        for (int mt = 0; mt < 4; mt++)
            #pragma unroll
            for (int nt = 0; nt < 4; nt++) {
                uint32_t addr = redb + (uint32_t)(((mt * 4 + nt) * 32 + lane) * 16);
                asm volatile("st.shared.v4.b32 [%0], {%1,%2,%3,%4};" ::"r"(addr),
                             "r"(__float_as_uint(cc[mt][nt][0])),
                             "r"(__float_as_uint(cc[mt][nt][1])),
                             "r"(__float_as_uint(cc[mt][nt][2])),
                             "r"(__float_as_uint(cc[mt][nt][3])) : "memory");
            }
    }
    __syncthreads();
    if (wk == 0) {
        #pragma unroll
        for (int mt = 0; mt < 4; mt++)
            #pragma unroll
            for (int nt = 0; nt < 4; nt++) {
                uint32_t addr = redb + (uint32_t)(((mt * 4 + nt) * 32 + lane) * 16);
                uint32_t r0, r1, r2, r3;
                asm volatile("ld.shared.v4.b32 {%0,%1,%2,%3}, [%4];"
                             : "=r"(r0), "=r"(r1), "=r"(r2), "=r"(r3) : "r"(addr));
                cc[mt][nt][0] += __uint_as_float(r0);
                cc[mt][nt][1] += __uint_as_float(r1);
                cc[mt][nt][2] += __uint_as_float(r2);
                cc[mt][nt][3] += __uint_as_float(r3);
            }
    }
    __syncthreads();  // reduction slots reused as pipeline buffers next block
}

// ---------------- GEMM1: X @ Wgu^T (+SwiGLU) -> g_h (fp16) ----------------
// B rows interleave gate/up by parity (64 B-rows = 32 h-cols).
__global__ void __launch_bounds__(256, 2)
gemm1_k() {
    const int e = blockIdx.z;
    const int base = g_offsets[e];
    const int n_e = g_offsets[e + 1] - base;
    const int col0 = blockIdx.y * 32;  // h columns per tile

    extern __shared__ __align__(128) char smraw[];
    const uint32_t smem0 = cvta_s(smraw);
    const int tid = threadIdx.x;
    const int lane = tid & 31, warp = tid >> 5;
    const int wk = warp >> 2;
    const int wm = (warp >> 1) & 1, wn = warp & 1;
    const uint32_t wb = smem0 + (uint32_t)(warp * W_REGION);
    const int koff = wk * 16;

    // this lane's private B row (n = wn*32 + lane), gate/up parity interleave
    const int n = wn * 32 + lane;
    const int wrow = col0 + (n >> 1) + ((n & 1) ? F_DIM : 0);
    const __half* b_ptr = g_wguh + ((size_t)e * F2_DIM + wrow) * D_DIM;

    for (int rb2 = blockIdx.x; rb2 * 128 < n_e; rb2 += GRIDX) {
        const int row0 = rb2 * 128;
        int ge0 = base + row0 + wm * 64 + lane;
        int ge1 = ge0 + 32;
        if (ge0 > TK - 1) ge0 = TK - 1;
        if (ge1 > TK - 1) ge1 = TK - 1;
        const __half* a_ptr0 = g_xh + (size_t)g_tok[ge0] * D_DIM;
        const __half* a_ptr1 = g_xh + (size_t)g_tok[ge1] * D_DIM;

        float cc[4][4][4];
        #pragma unroll
        for (int a = 0; a < 4; a++)
            #pragma unroll
            for (int b = 0; b < 4; b++)
                #pragma unroll
                for (int c = 0; c < 4; c++) cc[a][b][c] = 0.f;

        mma_loop(wb, a_ptr0, a_ptr1, b_ptr, koff, D_DIM / 32, cc);
        ksplit_reduce(smem0, warp, lane, wk, cc);

        if (wk == 0) {
            const int rbase = wm * 64 + (lane >> 2);
            const int jbase = col0 + wn * 16 + (lane & 3);
            #pragma unroll
            for (int mt = 0; mt < 4; mt++) {
                const int r0 = rbase + mt * 16;
                #pragma unroll
                for (int nt = 0; nt < 4; nt++) {
                    const int j = jbase + (nt >> 1) * 8 + (nt & 1) * 4;
                    if (row0 + r0 < n_e) {
                        float g = cc[mt][nt][0], u = cc[mt][nt][1];
                        float h = g * u / (1.f + __expf(-g));
                        g_h[(size_t)(base + row0 + r0) * F_DIM + j] = __float2half_rn(h);
                    }
                    if (row0 + r0 + 8 < n_e) {
                        float g = cc[mt][nt][2], u = cc[mt][nt][3];
                        float h = g * u / (1.f + __expf(-g));
                        g_h[(size_t)(base + row0 + r0 + 8) * F_DIM + j] = __float2half_rn(h);
                    }
                }
            }
        }
    }
}

// ---------------- GEMM2: g_h @ Wd^T, scale, per-slot store ----------------
__global__ void __launch_bounds__(256, 2)
gemm2_k() {
    const int e = blockIdx.z;
    const int base = g_offsets[e];
    const int n_e = g_offsets[e + 1] - base;
    const int col0 = blockIdx.y * 64;  // over D

    extern __shared__ __align__(128) char smraw[];
    const uint32_t smem0 = cvta_s(smraw);
    const int tid = threadIdx.x;
    const int lane = tid & 31, warp = tid >> 5;
    const int wk = warp >> 2;
    const int wm = (warp >> 1) & 1, wn = warp & 1;
    const uint32_t wb = smem0 + (uint32_t)(warp * W_REGION);
    const int koff = wk * 16;

    const __half* b_ptr = g_wdh + ((size_t)e * D_DIM + col0 + wn * 32 + lane) * F_DIM;

    for (int rb2 = blockIdx.x; rb2 * 128 < n_e; rb2 += GRIDX) {
        const int row0 = rb2 * 128;
        int ge0 = base + row0 + wm * 64 + lane;
        int ge1 = ge0 + 32;
        if (ge0 > TK - 1) ge0 = TK - 1;
        if (ge1 > TK - 1) ge1 = TK - 1;
        const __half* a_ptr0 = g_h + (size_t)ge0 * F_DIM;
        const __half* a_ptr1 = g_h + (size_t)ge1 * F_DIM;

        float cc[4][4][4];
        #pragma unroll
        for (int a = 0; a < 4; a++)
            #pragma unroll
            for (int b = 0; b < 4; b++)
                #pragma unroll
                for (int c = 0; c < 4; c++) cc[a][b][c] = 0.f;

        mma_loop(wb, a_ptr0, a_ptr1, b_ptr, koff, F_DIM / 32, cc);
        ksplit_reduce(smem0, warp, lane, wk, cc);

        if (wk == 0) {
            const int rbase = wm * 64 + (lane >> 2);
            const int colb = col0 + wn * 32 + 2 * (lane & 3);
            #pragma unroll
            for (int mt = 0; mt < 4; mt++) {
                const int r0 = rbase + mt * 16;
                #pragma unroll
                for (int half = 0; half < 2; half++) {
                    const int r = r0 + half * 8;
                    if (row0 + r < n_e) {
                        const int gi = base + row0 + r;
                        const int pos = g_pos[gi];
                        const float wt = g_wt[gi];
                        float* orow = g_o + (size_t)pos * D_DIM;
                        #pragma unroll
                        for (int nt = 0; nt < 4; nt++) {
                            const int col = colb + (nt >> 1) * 16 + (nt & 1) * 8;
                            float2 v;
                            v.x = cc[mt][nt][half * 2 + 0] * wt;
                            v.y = cc[mt][nt][half * 2 + 1] * wt;
                            *(float2*)(orow + col) = v;
                        }
                    }
                }
            }
        }
    }
}

// ---------------- combine the 2 slots per token ----------------
__global__ void combine_kernel(float4* __restrict__ out) {
    const int RD = D_DIM / 4;
    int i = blockIdx.x * blockDim.x + threadIdx.x;
    if (i < T_TOK * RD) {
        int t = i / RD, r = i % RD;
        const float4* go = (const float4*)g_o;
        float4 a = go[(size_t)(2 * t) * RD + r];
        float4 b = go[(size_t)(2 * t + 1) * RD + r];
        out[i] = make_float4(a.x + b.x, a.y + b.y, a.z + b.z, a.w + b.w);
    }
}

// ---------------- launch ----------------
extern "C" void kernel_launch(void* const* d_in, const int* in_sizes, int n_in,
                              void* d_out, int out_size) {
    const float* X   = (const float*)d_in[0];
    const float* rw  = (const float*)d_in[1];
    const float* Wgu = (const float*)d_in[2];
    const float* Wd  = (const float*)d_in[3];
    const void*  sel = d_in[4];
    float* out = (float*)d_out;

    cudaFuncSetAttribute(gemm1_k, cudaFuncAttributeMaxDynamicSharedMemorySize, SMEM_BYTES);
    cudaFuncSetAttribute(gemm2_k, cudaFuncAttributeMaxDynamicSharedMemorySize, SMEM_BYTES);

    cvt_all<<<2048, 256>>>((const float4*)X, (const float4*)Wgu, (const float4*)Wd);
    routing_kernel<<<1, 1024>>>(sel, rw);
    gemm1_k<<<dim3(GRIDX, F_DIM / 32, N_EXP), 256, SMEM_BYTES>>>();
    gemm2_k<<<dim3(GRIDX, D_DIM / 64, N_EXP), 256, SMEM_BYTES>>>();
    combine_kernel<<<(T_TOK * D_DIM / 4 + 255) / 256, 256>>>((float4*)out);
}

// round 14
// speedup vs baseline: 2.5020x; 2.5020x over previous
#include <cuda_runtime.h>
#include <cuda_fp16.h>
#include <cstdint>
#include <cstddef>

// ---------------- problem constants ----------------
#define T_TOK 4096
#define D_DIM 1024
#define F_DIM 2816
#define F2_DIM 5632
#define N_EXP 8
#define TK 8192

// ---------------- tiling ----------------
// fp16: BM=128, BN=64, BK=32, 256 threads, warps 2m x 2n x 2k
// (warp tile 64m x 32n x k16 via m16n8k16), 2 CTAs/SM.
// Pipeline depth per kernel: gemm1 = 8 stages (7 in flight),
// gemm2 = 6 stages (5 in flight)  [R10 empirical optimum].
#define A_ST 8192                      // 128 rows * 64 B
#define B_ST 4096                      // 64 rows * 64 B
#define STAGE_BYTES (A_ST + B_ST)      // 12 KB
#define NST1 8
#define NST2 6
#define SMEM1 (NST1 * STAGE_BYTES)     // 96 KB
#define SMEM2 (NST2 * STAGE_BYTES)     // 72 KB
#define GRIDX 9

// ---------------- device scratch ----------------
__device__ int    g_offsets[N_EXP + 1];
__device__ int    g_tok[TK];
__device__ int    g_pos[TK];
__device__ float  g_wt[TK];
__device__ __half g_xh[(size_t)T_TOK * D_DIM];
__device__ __half g_wguh[(size_t)N_EXP * F2_DIM * D_DIM];
__device__ __half g_wdh[(size_t)N_EXP * D_DIM * F_DIM];
__device__ __half g_h[(size_t)TK * F_DIM];
__device__ float  g_o[(size_t)TK * D_DIM];

// ---------------- helpers ----------------
__device__ __forceinline__ uint32_t cvta_s(const void* p) {
    return (uint32_t)__cvta_generic_to_shared(p);
}
__device__ __forceinline__ void cpasync16(uint32_t smem_addr, const void* gptr) {
    asm volatile("cp.async.cg.shared.global [%0], [%1], 16;" ::"r"(smem_addr), "l"(gptr));
}
__device__ __forceinline__ void cp_commit() { asm volatile("cp.async.commit_group;"); }
__device__ __forceinline__ void cp_waitg(int left) {
    if (left <= 0) asm volatile("cp.async.wait_group 0;");
    else if (left == 1) asm volatile("cp.async.wait_group 1;");
    else if (left == 2) asm volatile("cp.async.wait_group 2;");
    else if (left == 3) asm volatile("cp.async.wait_group 3;");
    else if (left == 4) asm volatile("cp.async.wait_group 4;");
    else if (left == 5) asm volatile("cp.async.wait_group 5;");
    else asm volatile("cp.async.wait_group 6;");
}
__device__ __forceinline__ void ldsm4(uint32_t r[4], uint32_t addr) {
    asm volatile("ldmatrix.sync.aligned.m8n8.x4.shared.b16 {%0,%1,%2,%3}, [%4];"
                 : "=r"(r[0]), "=r"(r[1]), "=r"(r[2]), "=r"(r[3]) : "r"(addr));
}
__device__ __forceinline__ void mma_f16(float c[4], const uint32_t a[4],
                                        uint32_t b0, uint32_t b1) {
    asm volatile(
        "mma.sync.aligned.m16n8k16.row.col.f32.f16.f16.f32 "
        "{%0,%1,%2,%3},{%4,%5,%6,%7},{%8,%9},{%0,%1,%2,%3};"
        : "+f"(c[0]), "+f"(c[1]), "+f"(c[2]), "+f"(c[3])
        : "r"(a[0]), "r"(a[1]), "r"(a[2]), "r"(a[3]), "r"(b0), "r"(b1));
}

// ---------------- convert f32 inputs to fp16 ----------------
__global__ void cvt_all(const float4* __restrict__ x, const float4* __restrict__ wgu,
                        const float4* __restrict__ wd) {
    const int NX = T_TOK * D_DIM / 4;
    const int NG = N_EXP * F2_DIM * D_DIM / 4;
    const int ND = N_EXP * D_DIM * F_DIM / 4;
    const int total = NX + NG + ND;
    for (int i = blockIdx.x * blockDim.x + threadIdx.x; i < total;
         i += gridDim.x * blockDim.x) {
        const float4* s;
        __half2* d;
        int j;
        if (i < NX)           { s = x;   d = (__half2*)g_xh;   j = i; }
        else if (i < NX + NG) { s = wgu; d = (__half2*)g_wguh; j = i - NX; }
        else                  { s = wd;  d = (__half2*)g_wdh;  j = i - NX - NG; }
        float4 v = s[j];
        d[2 * j]     = __float22half2_rn(make_float2(v.x, v.y));
        d[2 * j + 1] = __float22half2_rn(make_float2(v.z, v.w));
    }
}

// ---------------- routing ----------------
__global__ void routing_kernel(const void* sel_raw, const float* __restrict__ rw) {
    __shared__ int sc[N_EXP];
    __shared__ int scur[N_EXP];
    __shared__ int smode;
    int tid = threadIdx.x;
    if (tid < N_EXP) sc[tid] = 0;
    if (tid == 0) {
        const int* s32 = (const int*)sel_raw;
        int any = 0;
        #pragma unroll
        for (int i = 0; i < 8; i++) any |= s32[2 * i + 1];
        smode = any ? 0 : 1;  // 1 = int64
    }
    __syncthreads();
    int mode = smode;
    const long long* s64 = (const long long*)sel_raw;
    const int* s32 = (const int*)sel_raw;
    for (int i = tid; i < TK; i += blockDim.x) {
        int e = mode ? (int)s64[i] : s32[i];
        atomicAdd(&sc[e], 1);
    }
    __syncthreads();
    if (tid == 0) {
        int off = 0;
        for (int e = 0; e < N_EXP; e++) { g_offsets[e] = off; scur[e] = off; off += sc[e]; }
        g_offsets[N_EXP] = off;
    }
    __syncthreads();
    for (int i = tid; i < TK; i += blockDim.x) {
        int e = mode ? (int)s64[i] : s32[i];
        int p = atomicAdd(&scur[e], 1);
        g_tok[p] = i >> 1;
        g_pos[p] = i;
        g_wt[p] = rw[i];
    }
}

// ---------------- shared fp16 mainloop (BK=32, templated depth) ----------------
// Stage: [A 8KB: 128 rows x 64B][B 4KB: 64 rows x 64B].
// Swizzle: 16B chunk c of row r at r*64 + ((c ^ ((r>>1)&3))<<4).
// Warp (wk=warp>>2, wm=(warp>>1)&1, wn=warp&1): 64m x 32n over k-half wk (k16).
template <int NST>
__device__ __forceinline__ void mma_loop(uint32_t smem0, const __half* a_row,
                                         const __half* b_row, int KT,
                                         float cc[4][4][4]) {
    const int tid = threadIdx.x;
    const int lane = tid & 31;
    const int warp = tid >> 5;
    const int wk = warp >> 2;
    const int wm = (warp >> 1) & 1;
    const int wn = warp & 1;
    constexpr int INFLIGHT = NST - 1;   // groups in flight
    constexpr int WAITCAP = NST - 2;

    // loader: A row = tid>>1 (2 chunks), B row = tid>>2 (1 chunk)
    const int ra = tid >> 1;
    const int rb = tid >> 2;
    uint32_t stA[2], stB;
    #pragma unroll
    for (int i = 0; i < 2; i++) {
        const int c = (tid & 1) * 2 + i;
        stA[i] = (uint32_t)(ra * 64) + (uint32_t)(((c ^ ((ra >> 1) & 3)) << 4));
    }
    {
        const int c = tid & 3;
        stB = (uint32_t)(A_ST + rb * 64) + (uint32_t)(((c ^ ((rb >> 1) & 3)) << 4));
    }

    // ldsm addresses (stage-relative)
    const int arow_l = (lane & 7) + (lane & 8);
    const int brow_l = (lane & 7) + ((lane >> 4) << 3);
    const int achunk = 2 * wk + (lane >> 4);
    const int bchunk = 2 * wk + ((lane >> 3) & 1);
    uint32_t a_off[4], b_off[2];
    #pragma unroll
    for (int mt = 0; mt < 4; mt++) {
        const int row = wm * 64 + mt * 16 + arow_l;
        a_off[mt] = (uint32_t)(row * 64) +
                    (uint32_t)(((achunk ^ ((arow_l >> 1) & 3)) << 4));
    }
    #pragma unroll
    for (int n2 = 0; n2 < 2; n2++) {
        const int row = wn * 32 + n2 * 16 + brow_l;
        b_off[n2] = (uint32_t)(A_ST + row * 64) +
                    (uint32_t)(((bchunk ^ ((brow_l >> 1) & 3)) << 4));
    }

    auto load_stage = [&](int kt) {
        const uint32_t sb = smem0 + (uint32_t)((kt % NST) * STAGE_BYTES);
        const __half* As = a_row + kt * 32;
        const __half* Bs = b_row + kt * 32;
        #pragma unroll
        for (int i = 0; i < 2; i++)
            cpasync16(sb + stA[i], As + ((tid & 1) * 2 + i) * 8);
        cpasync16(sb + stB, Bs + (tid & 3) * 8);
        cp_commit();
    };

    // preload (KT >= 32 always here, so INFLIGHT <= 7 < KT)
    #pragma unroll
    for (int s = 0; s < INFLIGHT; s++) load_stage(s);

    for (int kt = 0; kt < KT; kt++) {
        const int rem = KT - 1 - kt;
        cp_waitg(rem < WAITCAP ? rem : WAITCAP);
        __syncthreads();
        if (kt + INFLIGHT < KT) load_stage(kt + INFLIGHT);

        const uint32_t base = smem0 + (uint32_t)((kt % NST) * STAGE_BYTES);
        uint32_t a[4][4], b[2][4];
        #pragma unroll
        for (int mt = 0; mt < 4; mt++)
            ldsm4(a[mt], base + a_off[mt]);
        #pragma unroll
        for (int n2 = 0; n2 < 2; n2++)
            ldsm4(b[n2], base + b_off[n2]);
        #pragma unroll
        for (int mt = 0; mt < 4; mt++)
            #pragma unroll
            for (int nt = 0; nt < 4; nt++)
                mma_f16(cc[mt][nt], a[mt], b[nt >> 1][(nt & 1) * 2],
                        b[nt >> 1][(nt & 1) * 2 + 1]);
    }

    // k-split reduction: warp pairs (w, w+4) share (wm, wn); 8KB slot each.
    __syncthreads();
    const uint32_t redb = smem0 + (uint32_t)((warp & 3) * 8192);
    if (wk == 1) {
        #pragma unroll
        for (int mt = 0; mt < 4; mt++)
            #pragma unroll
            for (int nt = 0; nt < 4; nt++) {
                uint32_t addr = redb + (uint32_t)(((mt * 4 + nt) * 32 + lane) * 16);
                asm volatile("st.shared.v4.b32 [%0], {%1,%2,%3,%4};" ::"r"(addr),
                             "r"(__float_as_uint(cc[mt][nt][0])),
                             "r"(__float_as_uint(cc[mt][nt][1])),
                             "r"(__float_as_uint(cc[mt][nt][2])),
                             "r"(__float_as_uint(cc[mt][nt][3])) : "memory");
            }
    }
    __syncthreads();
    if (wk == 0) {
        #pragma unroll
        for (int mt = 0; mt < 4; mt++)
            #pragma unroll
            for (int nt = 0; nt < 4; nt++) {
                uint32_t addr = redb + (uint32_t)(((mt * 4 + nt) * 32 + lane) * 16);
                uint32_t r0, r1, r2, r3;
                asm volatile("ld.shared.v4.b32 {%0,%1,%2,%3}, [%4];"
                             : "=r"(r0), "=r"(r1), "=r"(r2), "=r"(r3) : "r"(addr));
                cc[mt][nt][0] += __uint_as_float(r0);
                cc[mt][nt][1] += __uint_as_float(r1);
                cc[mt][nt][2] += __uint_as_float(r2);
                cc[mt][nt][3] += __uint_as_float(r3);
            }
    }
    __syncthreads();  // reduce reads done before next row-block's loads
}

// ---------------- GEMM1: X @ Wgu^T (+SwiGLU) -> g_h (fp16) ----------------
// B rows interleave gate/up by parity (64 B-rows = 32 h-cols).
__global__ void __launch_bounds__(256, 2)
gemm1_k() {
    const int e = blockIdx.z;
    const int base = g_offsets[e];
    const int n_e = g_offsets[e + 1] - base;
    const int col0 = blockIdx.y * 32;  // h columns per tile

    extern __shared__ __align__(128) char smraw[];
    const uint32_t smem0 = cvta_s(smraw);
    const int tid = threadIdx.x;
    const int lane = tid & 31, warp = tid >> 5;
    const int wk = warp >> 2;
    const int wm = (warp >> 1) & 1, wn = warp & 1;

    const int nrow = tid >> 2;
    const int wrow = col0 + (nrow >> 1) + ((nrow & 1) ? F_DIM : 0);
    const __half* b_row = g_wguh + ((size_t)e * F2_DIM + wrow) * D_DIM;

    for (int rb2 = blockIdx.x; rb2 * 128 < n_e; rb2 += GRIDX) {
        const int row0 = rb2 * 128;
        int ge = base + row0 + (tid >> 1);
        if (ge > TK - 1) ge = TK - 1;
        const __half* a_row = g_xh + (size_t)g_tok[ge] * D_DIM;

        float cc[4][4][4];
        #pragma unroll
        for (int a = 0; a < 4; a++)
            #pragma unroll
            for (int b = 0; b < 4; b++)
                #pragma unroll
                for (int c = 0; c < 4; c++) cc[a][b][c] = 0.f;

        mma_loop<NST1>(smem0, a_row, b_row, D_DIM / 32, cc);

        if (wk == 0) {
            const int rbase = wm * 64 + (lane >> 2);
            const int jbase = col0 + wn * 16 + (lane & 3);
            #pragma unroll
            for (int mt = 0; mt < 4; mt++) {
                const int r0 = rbase + mt * 16;
                #pragma unroll
                for (int nt = 0; nt < 4; nt++) {
                    const int j = jbase + (nt >> 1) * 8 + (nt & 1) * 4;
                    if (row0 + r0 < n_e) {
                        float g = cc[mt][nt][0], u = cc[mt][nt][1];
                        float h = g * u / (1.f + __expf(-g));
                        g_h[(size_t)(base + row0 + r0) * F_DIM + j] = __float2half_rn(h);
                    }
                    if (row0 + r0 + 8 < n_e) {
                        float g = cc[mt][nt][2], u = cc[mt][nt][3];
                        float h = g * u / (1.f + __expf(-g));
                        g_h[(size_t)(base + row0 + r0 + 8) * F_DIM + j] = __float2half_rn(h);
                    }
                }
            }
        }
    }
}

// ---------------- GEMM2: g_h @ Wd^T, scale, per-slot store ----------------
__global__ void __launch_bounds__(256, 2)
gemm2_k() {
    const int e = blockIdx.z;
    const int base = g_offsets[e];
    const int n_e = g_offsets[e + 1] - base;
    const int col0 = blockIdx.y * 64;  // over D

    extern __shared__ __align__(128) char smraw[];
    const uint32_t smem0 = cvta_s(smraw);
    const int tid = threadIdx.x;
    const int lane = tid & 31, warp = tid >> 5;
    const int wk = warp >> 2;
    const int wm = (warp >> 1) & 1, wn = warp & 1;

    const __half* b_row = g_wdh + ((size_t)e * D_DIM + col0 + (tid >> 2)) * F_DIM;

    for (int rb2 = blockIdx.x; rb2 * 128 < n_e; rb2 += GRIDX) {
        const int row0 = rb2 * 128;
        int ge = base + row0 + (tid >> 1);
        if (ge > TK - 1) ge = TK - 1;
        const __half* a_row = g_h + (size_t)ge * F_DIM;

        float cc[4][4][4];
        #pragma unroll
        for (int a = 0; a < 4; a++)
            #pragma unroll
            for (int b = 0; b < 4; b++)
                #pragma unroll
                for (int c = 0; c < 4; c++) cc[a][b][c] = 0.f;

        mma_loop<NST2>(smem0, a_row, b_row, F_DIM / 32, cc);

        if (wk == 0) {
            const int rbase = wm * 64 + (lane >> 2);
            const int colb = col0 + wn * 32 + 2 * (lane & 3);
            #pragma unroll
            for (int mt = 0; mt < 4; mt++) {
                const int r0 = rbase + mt * 16;
                #pragma unroll
                for (int half = 0; half < 2; half++) {
                    const int r = r0 + half * 8;
                    if (row0 + r < n_e) {
                        const int gi = base + row0 + r;
                        const int pos = g_pos[gi];
                        const float wt = g_wt[gi];
                        float* orow = g_o + (size_t)pos * D_DIM;
                        #pragma unroll
                        for (int nt = 0; nt < 4; nt++) {
                            const int col = colb + (nt >> 1) * 16 + (nt & 1) * 8;
                            float2 v;
                            v.x = cc[mt][nt][half * 2 + 0] * wt;
                            v.y = cc[mt][nt][half * 2 + 1] * wt;
                            *(float2*)(orow + col) = v;
                        }
                    }
                }
            }
        }
    }
}

// ---------------- combine the 2 slots per token ----------------
__global__ void combine_kernel(float4* __restrict__ out) {
    const int RD = D_DIM / 4;
    int i = blockIdx.x * blockDim.x + threadIdx.x;
    if (i < T_TOK * RD) {
        int t = i / RD, r = i % RD;
        const float4* go = (const float4*)g_o;
        float4 a = go[(size_t)(2 * t) * RD + r];
        float4 b = go[(size_t)(2 * t + 1) * RD + r];
        out[i] = make_float4(a.x + b.x, a.y + b.y, a.z + b.z, a.w + b.w);
    }
}

// ---------------- launch ----------------
extern "C" void kernel_launch(void* const* d_in, const int* in_sizes, int n_in,
                              void* d_out, int out_size) {
    const float* X   = (const float*)d_in[0];
    const float* rw  = (const float*)d_in[1];
    const float* Wgu = (const float*)d_in[2];
    const float* Wd  = (const float*)d_in[3];
    const void*  sel = d_in[4];
    float* out = (float*)d_out;

    cudaFuncSetAttribute(gemm1_k, cudaFuncAttributeMaxDynamicSharedMemorySize, SMEM1);
    cudaFuncSetAttribute(gemm2_k, cudaFuncAttributeMaxDynamicSharedMemorySize, SMEM2);

    cvt_all<<<2048, 256>>>((const float4*)X, (const float4*)Wgu, (const float4*)Wd);
    routing_kernel<<<1, 1024>>>(sel, rw);
    gemm1_k<<<dim3(GRIDX, F_DIM / 32, N_EXP), 256, SMEM1>>>();
    gemm2_k<<<dim3(GRIDX, D_DIM / 64, N_EXP), 256, SMEM2>>>();
    combine_kernel<<<(T_TOK * D_DIM / 4 + 255) / 256, 256>>>((float4*)out);
}

// round 15
// speedup vs baseline: 2.8966x; 1.1577x over previous
#include <cuda_runtime.h>
#include <cuda_fp16.h>
#include <cstdint>
#include <cstddef>

// ---------------- problem constants ----------------
#define T_TOK 4096
#define D_DIM 1024
#define F_DIM 2816
#define F2_DIM 5632
#define N_EXP 8
#define TK 8192

// ---------------- tiling (R10 optimum) ----------------
// fp16: BM=128, BN=64, BK=32, 256 threads, warps 2m x 2n x 2k,
// 6-stage cp.async (5 in flight), 2 CTAs/SM.
#define N_ST 6
#define A_ST 8192                      // 128 rows * 64 B
#define B_ST 4096                      // 64 rows * 64 B
#define STAGE_BYTES (A_ST + B_ST)      // 12 KB
#define SMEM_BYTES (N_ST * STAGE_BYTES)  // 72 KB
#define GRIDX 9
#define NCVT 1024                      // prep kernel conversion blocks
#define G1Y (F_DIM / 32)               // 88 gemm tiles in y
#define WDCVT_Y 4                      // extra y-blocks in gemm1 for Wd cvt

// ---------------- device scratch ----------------
__device__ int    g_offsets[N_EXP + 1];
__device__ int    g_tok[TK];
__device__ int    g_pos[TK];
__device__ float  g_wt[TK];
__device__ __half g_xh[(size_t)T_TOK * D_DIM];
__device__ __half g_wguh[(size_t)N_EXP * F2_DIM * D_DIM];
__device__ __half g_wdh[(size_t)N_EXP * D_DIM * F_DIM];
__device__ __half g_h[(size_t)TK * F_DIM];
__device__ float  g_o[(size_t)TK * D_DIM];

// ---------------- helpers ----------------
__device__ __forceinline__ uint32_t cvta_s(const void* p) {
    return (uint32_t)__cvta_generic_to_shared(p);
}
__device__ __forceinline__ void cpasync16(uint32_t smem_addr, const void* gptr) {
    asm volatile("cp.async.cg.shared.global [%0], [%1], 16;" ::"r"(smem_addr), "l"(gptr));
}
__device__ __forceinline__ void cp_commit() { asm volatile("cp.async.commit_group;"); }
__device__ __forceinline__ void cp_waitg(int left) {
    if (left <= 0) asm volatile("cp.async.wait_group 0;");
    else if (left == 1) asm volatile("cp.async.wait_group 1;");
    else if (left == 2) asm volatile("cp.async.wait_group 2;");
    else if (left == 3) asm volatile("cp.async.wait_group 3;");
    else asm volatile("cp.async.wait_group 4;");
}
__device__ __forceinline__ void ldsm4(uint32_t r[4], uint32_t addr) {
    asm volatile("ldmatrix.sync.aligned.m8n8.x4.shared.b16 {%0,%1,%2,%3}, [%4];"
                 : "=r"(r[0]), "=r"(r[1]), "=r"(r[2]), "=r"(r[3]) : "r"(addr));
}
__device__ __forceinline__ void mma_f16(float c[4], const uint32_t a[4],
                                        uint32_t b0, uint32_t b1) {
    asm volatile(
        "mma.sync.aligned.m16n8k16.row.col.f32.f16.f16.f32 "
        "{%0,%1,%2,%3},{%4,%5,%6,%7},{%8,%9},{%0,%1,%2,%3};"
        : "+f"(c[0]), "+f"(c[1]), "+f"(c[2]), "+f"(c[3])
        : "r"(a[0]), "r"(a[1]), "r"(a[2]), "r"(a[3]), "r"(b0), "r"(b1));
}
__device__ __forceinline__ uint32_t pack_h2(float x, float y) {
    __half2 h = __float22half2_rn(make_float2(x, y));
    return *reinterpret_cast<uint32_t*>(&h);
}

// ---------------- prep: convert X + Wgu, plus routing block ----------------
__global__ void prep_kernel(const float4* __restrict__ x, const float4* __restrict__ wgu,
                            const float* __restrict__ rw, const void* sel_raw) {
    if (blockIdx.x == NCVT) {
        // ---- routing (one block) ----
        __shared__ int sc[N_EXP];
        __shared__ int scur[N_EXP];
        __shared__ int smode;
        int tid = threadIdx.x;
        if (tid < N_EXP) sc[tid] = 0;
        if (tid == 0) {
            const int* s32 = (const int*)sel_raw;
            int any = 0;
            #pragma unroll
            for (int i = 0; i < 8; i++) any |= s32[2 * i + 1];
            smode = any ? 0 : 1;  // 1 = int64
        }
        __syncthreads();
        int mode = smode;
        const long long* s64 = (const long long*)sel_raw;
        const int* s32 = (const int*)sel_raw;
        for (int i = tid; i < TK; i += blockDim.x) {
            int e = mode ? (int)s64[i] : s32[i];
            atomicAdd(&sc[e], 1);
        }
        __syncthreads();
        if (tid == 0) {
            int off = 0;
            for (int e = 0; e < N_EXP; e++) { g_offsets[e] = off; scur[e] = off; off += sc[e]; }
            g_offsets[N_EXP] = off;
        }
        __syncthreads();
        for (int i = tid; i < TK; i += blockDim.x) {
            int e = mode ? (int)s64[i] : s32[i];
            int p = atomicAdd(&scur[e], 1);
            g_tok[p] = i >> 1;
            g_pos[p] = i;
            g_wt[p] = rw[i];
        }
        return;
    }
    // ---- conversion: 8 floats per iteration (2 float4 in, 1 uint4 out) ----
    const int NX8 = T_TOK * D_DIM / 8;                  // 524288
    const int NG8 = N_EXP * F2_DIM * D_DIM / 8;         // 5767168
    const int total = NX8 + NG8;
    for (int i = blockIdx.x * blockDim.x + threadIdx.x; i < total;
         i += NCVT * blockDim.x) {
        const float4* s;
        uint4* d;
        int j;
        if (i < NX8) { s = x;   d = (uint4*)g_xh;   j = i; }
        else         { s = wgu; d = (uint4*)g_wguh; j = i - NX8; }
        float4 v0 = s[2 * j];
        float4 v1 = s[2 * j + 1];
        uint4 o;
        o.x = pack_h2(v0.x, v0.y);
        o.y = pack_h2(v0.z, v0.w);
        o.z = pack_h2(v1.x, v1.y);
        o.w = pack_h2(v1.z, v1.w);
        d[j] = o;
    }
}

// ---------------- shared fp16 mainloop (R10: BK=32, 6 stages) ----------------
// Stage: [A 8KB: 128 rows x 64B][B 4KB: 64 rows x 64B].
// Swizzle: 16B chunk c of row r at r*64 + ((c ^ ((r>>1)&3))<<4).
// Warp (wk=warp>>2, wm=(warp>>1)&1, wn=warp&1): 64m x 32n over k-half wk (k16).
__device__ __forceinline__ void mma_loop(uint32_t smem0, const __half* a_row,
                                         const __half* b_row, int KT,
                                         float cc[4][4][4]) {
    const int tid = threadIdx.x;
    const int lane = tid & 31;
    const int warp = tid >> 5;
    const int wk = warp >> 2;
    const int wm = (warp >> 1) & 1;
    const int wn = warp & 1;

    const int ra = tid >> 1;
    const int rb = tid >> 2;
    uint32_t stA[2], stB;
    #pragma unroll
    for (int i = 0; i < 2; i++) {
        const int c = (tid & 1) * 2 + i;
        stA[i] = (uint32_t)(ra * 64) + (uint32_t)(((c ^ ((ra >> 1) & 3)) << 4));
    }
    {
        const int c = tid & 3;
        stB = (uint32_t)(A_ST + rb * 64) + (uint32_t)(((c ^ ((rb >> 1) & 3)) << 4));
    }

    const int arow_l = (lane & 7) + (lane & 8);
    const int brow_l = (lane & 7) + ((lane >> 4) << 3);
    const int achunk = 2 * wk + (lane >> 4);
    const int bchunk = 2 * wk + ((lane >> 3) & 1);
    uint32_t a_off[4], b_off[2];
    #pragma unroll
    for (int mt = 0; mt < 4; mt++) {
        const int row = wm * 64 + mt * 16 + arow_l;
        a_off[mt] = (uint32_t)(row * 64) +
                    (uint32_t)(((achunk ^ ((arow_l >> 1) & 3)) << 4));
    }
    #pragma unroll
    for (int n2 = 0; n2 < 2; n2++) {
        const int row = wn * 32 + n2 * 16 + brow_l;
        b_off[n2] = (uint32_t)(A_ST + row * 64) +
                    (uint32_t)(((bchunk ^ ((brow_l >> 1) & 3)) << 4));
    }

    auto load_stage = [&](int kt) {
        const uint32_t sb = smem0 + (uint32_t)((kt % N_ST) * STAGE_BYTES);
        const __half* As = a_row + kt * 32;
        const __half* Bs = b_row + kt * 32;
        #pragma unroll
        for (int i = 0; i < 2; i++)
            cpasync16(sb + stA[i], As + ((tid & 1) * 2 + i) * 8);
        cpasync16(sb + stB, Bs + (tid & 3) * 8);
        cp_commit();
    };

    #pragma unroll
    for (int s = 0; s < 5; s++) load_stage(s);

    for (int kt = 0; kt < KT; kt++) {
        const int rem = KT - 1 - kt;
        cp_waitg(rem < 4 ? rem : 4);
        __syncthreads();
        if (kt + 5 < KT) load_stage(kt + 5);

        const uint32_t base = smem0 + (uint32_t)((kt % N_ST) * STAGE_BYTES);
        uint32_t a[4][4], b[2][4];
        #pragma unroll
        for (int mt = 0; mt < 4; mt++)
            ldsm4(a[mt], base + a_off[mt]);
        #pragma unroll
        for (int n2 = 0; n2 < 2; n2++)
            ldsm4(b[n2], base + b_off[n2]);
        #pragma unroll
        for (int mt = 0; mt < 4; mt++)
            #pragma unroll
            for (int nt = 0; nt < 4; nt++)
                mma_f16(cc[mt][nt], a[mt], b[nt >> 1][(nt & 1) * 2],
                        b[nt >> 1][(nt & 1) * 2 + 1]);
    }

    // k-split reduction: warp pairs (w, w+4) share (wm, wn); 8KB slot each.
    __syncthreads();
    const uint32_t redb = smem0 + (uint32_t)((warp & 3) * 8192);
    if (wk == 1) {
        #pragma unroll
        for (int mt = 0; mt < 4; mt++)
            #pragma unroll
            for (int nt = 0; nt < 4; nt++) {
                uint32_t addr = redb + (uint32_t)(((mt * 4 + nt) * 32 + lane) * 16);
                asm volatile("st.shared.v4.b32 [%0], {%1,%2,%3,%4};" ::"r"(addr),
                             "r"(__float_as_uint(cc[mt][nt][0])),
                             "r"(__float_as_uint(cc[mt][nt][1])),
                             "r"(__float_as_uint(cc[mt][nt][2])),
                             "r"(__float_as_uint(cc[mt][nt][3])) : "memory");
            }
    }
    __syncthreads();
    if (wk == 0) {
        #pragma unroll
        for (int mt = 0; mt < 4; mt++)
            #pragma unroll
            for (int nt = 0; nt < 4; nt++) {
                uint32_t addr = redb + (uint32_t)(((mt * 4 + nt) * 32 + lane) * 16);
                uint32_t r0, r1, r2, r3;
                asm volatile("ld.shared.v4.b32 {%0,%1,%2,%3}, [%4];"
                             : "=r"(r0), "=r"(r1), "=r"(r2), "=r"(r3) : "r"(addr));
                cc[mt][nt][0] += __uint_as_float(r0);
                cc[mt][nt][1] += __uint_as_float(r1);
                cc[mt][nt][2] += __uint_as_float(r2);
                cc[mt][nt][3] += __uint_as_float(r3);
            }
    }
    __syncthreads();
}

// ---------------- GEMM1: X @ Wgu^T (+SwiGLU) -> g_h; extra blocks cvt Wd ----
__global__ void __launch_bounds__(256, 2)
gemm1_k(const float4* __restrict__ wd_src) {
    // ---- Wd conversion rider blocks (y >= G1Y) ----
    if (blockIdx.y >= G1Y) {
        const int cb = (blockIdx.z * WDCVT_Y + (blockIdx.y - G1Y)) * GRIDX + blockIdx.x;
        const int ND8 = N_EXP * D_DIM * F_DIM / 8;  // 2883584
        uint4* dst = (uint4*)g_wdh;
        const int nblk = GRIDX * WDCVT_Y * N_EXP;   // 288
        for (int i = cb * 256 + threadIdx.x; i < ND8; i += nblk * 256) {
            float4 v0 = wd_src[2 * i];
            float4 v1 = wd_src[2 * i + 1];
            uint4 o;
            o.x = pack_h2(v0.x, v0.y);
            o.y = pack_h2(v0.z, v0.w);
            o.z = pack_h2(v1.x, v1.y);
            o.w = pack_h2(v1.z, v1.w);
            dst[i] = o;
        }
        return;
    }

    const int e = blockIdx.z;
    const int base = g_offsets[e];
    const int n_e = g_offsets[e + 1] - base;
    const int col0 = blockIdx.y * 32;  // h columns per tile

    extern __shared__ __align__(128) char smraw[];
    const uint32_t smem0 = cvta_s(smraw);
    const int tid = threadIdx.x;
    const int lane = tid & 31, warp = tid >> 5;
    const int wk = warp >> 2;
    const int wm = (warp >> 1) & 1, wn = warp & 1;

    const int nrow = tid >> 2;
    const int wrow = col0 + (nrow >> 1) + ((nrow & 1) ? F_DIM : 0);
    const __half* b_row = g_wguh + ((size_t)e * F2_DIM + wrow) * D_DIM;

    for (int rb2 = blockIdx.x; rb2 * 128 < n_e; rb2 += GRIDX) {
        const int row0 = rb2 * 128;
        int ge = base + row0 + (tid >> 1);
        if (ge > TK - 1) ge = TK - 1;
        const __half* a_row = g_xh + (size_t)g_tok[ge] * D_DIM;

        float cc[4][4][4];
        #pragma unroll
        for (int a = 0; a < 4; a++)
            #pragma unroll
            for (int b = 0; b < 4; b++)
                #pragma unroll
                for (int c = 0; c < 4; c++) cc[a][b][c] = 0.f;

        mma_loop(smem0, a_row, b_row, D_DIM / 32, cc);

        if (wk == 0) {
            const int rbase = wm * 64 + (lane >> 2);
            const int jbase = col0 + wn * 16 + (lane & 3);
            #pragma unroll
            for (int mt = 0; mt < 4; mt++) {
                const int r0 = rbase + mt * 16;
                #pragma unroll
                for (int nt = 0; nt < 4; nt++) {
                    const int j = jbase + (nt >> 1) * 8 + (nt & 1) * 4;
                    if (row0 + r0 < n_e) {
                        float g = cc[mt][nt][0], u = cc[mt][nt][1];
                        float h = g * u / (1.f + __expf(-g));
                        g_h[(size_t)(base + row0 + r0) * F_DIM + j] = __float2half_rn(h);
                    }
                    if (row0 + r0 + 8 < n_e) {
                        float g = cc[mt][nt][2], u = cc[mt][nt][3];
                        float h = g * u / (1.f + __expf(-g));
                        g_h[(size_t)(base + row0 + r0 + 8) * F_DIM + j] = __float2half_rn(h);
                    }
                }
            }
        }
    }
}

// ---------------- GEMM2: g_h @ Wd^T, scale, per-slot store ----------------
__global__ void __launch_bounds__(256, 2)
gemm2_k() {
    const int e = blockIdx.z;
    const int base = g_offsets[e];
    const int n_e = g_offsets[e + 1] - base;
    const int col0 = blockIdx.y * 64;  // over D

    extern __shared__ __align__(128) char smraw[];
    const uint32_t smem0 = cvta_s(smraw);
    const int tid = threadIdx.x;
    const int lane = tid & 31, warp = tid >> 5;
    const int wk = warp >> 2;
    const int wm = (warp >> 1) & 1, wn = warp & 1;

    const __half* b_row = g_wdh + ((size_t)e * D_DIM + col0 + (tid >> 2)) * F_DIM;

    for (int rb2 = blockIdx.x; rb2 * 128 < n_e; rb2 += GRIDX) {
        const int row0 = rb2 * 128;
        int ge = base + row0 + (tid >> 1);
        if (ge > TK - 1) ge = TK - 1;
        const __half* a_row = g_h + (size_t)ge * F_DIM;

        float cc[4][4][4];
        #pragma unroll
        for (int a = 0; a < 4; a++)
            #pragma unroll
            for (int b = 0; b < 4; b++)
                #pragma unroll
                for (int c = 0; c < 4; c++) cc[a][b][c] = 0.f;

        mma_loop(smem0, a_row, b_row, F_DIM / 32, cc);

        if (wk == 0) {
            const int rbase = wm * 64 + (lane >> 2);
            const int colb = col0 + wn * 32 + 2 * (lane & 3);
            #pragma unroll
            for (int mt = 0; mt < 4; mt++) {
                const int r0 = rbase + mt * 16;
                #pragma unroll
                for (int half = 0; half < 2; half++) {
                    const int r = r0 + half * 8;
                    if (row0 + r < n_e) {
                        const int gi = base + row0 + r;
                        const int pos = g_pos[gi];
                        const float wt = g_wt[gi];
                        float* orow = g_o + (size_t)pos * D_DIM;
                        #pragma unroll
                        for (int nt = 0; nt < 4; nt++) {
                            const int col = colb + (nt >> 1) * 16 + (nt & 1) * 8;
                            float2 v;
                            v.x = cc[mt][nt][half * 2 + 0] * wt;
                            v.y = cc[mt][nt][half * 2 + 1] * wt;
                            *(float2*)(orow + col) = v;
                        }
                    }
                }
            }
        }
    }
}

// ---------------- combine the 2 slots per token ----------------
__global__ void combine_kernel(float4* __restrict__ out) {
    const int RD = D_DIM / 4;
    int i = blockIdx.x * blockDim.x + threadIdx.x;
    if (i < T_TOK * RD) {
        int t = i / RD, r = i % RD;
        const float4* go = (const float4*)g_o;
        float4 a = go[(size_t)(2 * t) * RD + r];
        float4 b = go[(size_t)(2 * t + 1) * RD + r];
        out[i] = make_float4(a.x + b.x, a.y + b.y, a.z + b.z, a.w + b.w);
    }
}

// ---------------- launch ----------------
extern "C" void kernel_launch(void* const* d_in, const int* in_sizes, int n_in,
                              void* d_out, int out_size) {
    const float* X   = (const float*)d_in[0];
    const float* rw  = (const float*)d_in[1];
    const float* Wgu = (const float*)d_in[2];
    const float* Wd  = (const float*)d_in[3];
    const void*  sel = d_in[4];
    float* out = (float*)d_out;

    cudaFuncSetAttribute(gemm1_k, cudaFuncAttributeMaxDynamicSharedMemorySize, SMEM_BYTES);
    cudaFuncSetAttribute(gemm2_k, cudaFuncAttributeMaxDynamicSharedMemorySize, SMEM_BYTES);

    prep_kernel<<<NCVT + 1, 256>>>((const float4*)X, (const float4*)Wgu, rw, sel);
    gemm1_k<<<dim3(GRIDX, G1Y + WDCVT_Y, N_EXP), 256, SMEM_BYTES>>>((const float4*)Wd);
    gemm2_k<<<dim3(GRIDX, D_DIM / 64, N_EXP), 256, SMEM_BYTES>>>();
    combine_kernel<<<(T_TOK * D_DIM / 4 + 255) / 256, 256>>>((float4*)out);
}